// round 2
// baseline (speedup 1.0000x reference)
#include <cuda_runtime.h>
#include <math.h>

#define BB 1024
#define SS 64
#define DD 256
#define CHN 1024
#define NCH 16   // sample chunk for hidden-layer register blocking

// scratch (device globals; no allocation allowed)
__device__ int   g_idx[BB];
__device__ __align__(16) float g_desc[2][BB][DD];     // gathered descriptors (t, rot)
__device__ __align__(16) float g_h[2][BB][CHN];       // gelu(hidden) activations

// ---------------------------------------------------------------------------
// K1: logits[b,s] = dot(cat(t[b,s], rot[b,s]), W_scene) + b_scene
// one warp per (b,s); 512-length dot via float4
// ---------------------------------------------------------------------------
__global__ void k_logits(const float* __restrict__ t, const float* __restrict__ r,
                         const float* __restrict__ Wsc, const float* __restrict__ bsc,
                         float* __restrict__ logits) {
    int w    = blockIdx.x * 8 + (threadIdx.x >> 5);   // global (b,s) index
    int lane = threadIdx.x & 31;
    if (w >= BB * SS) return;
    const float4* t4 = (const float4*)(t + (size_t)w * DD);
    const float4* r4 = (const float4*)(r + (size_t)w * DD);
    const float4* W4 = (const float4*)Wsc;            // 512 floats = 128 float4
    float acc = 0.f;
#pragma unroll
    for (int j = 0; j < 2; j++) {
        int k = j * 32 + lane;                        // k in [0,64)
        float4 a  = t4[k];
        float4 wa = W4[k];
        acc = fmaf(a.x, wa.x, acc); acc = fmaf(a.y, wa.y, acc);
        acc = fmaf(a.z, wa.z, acc); acc = fmaf(a.w, wa.w, acc);
        float4 b  = r4[k];
        float4 wb = W4[64 + k];
        acc = fmaf(b.x, wb.x, acc); acc = fmaf(b.y, wb.y, acc);
        acc = fmaf(b.z, wb.z, acc); acc = fmaf(b.w, wb.w, acc);
    }
#pragma unroll
    for (int o = 16; o; o >>= 1) acc += __shfl_down_sync(0xFFFFFFFFu, acc, o);
    if (lane == 0) logits[w] = acc + bsc[0];
}

// ---------------------------------------------------------------------------
// K2: per-sample log_softmax over S, argmax, and gather of selected descriptors
// one block (256 thr) per sample; in-place on the logits region of d_out
// ---------------------------------------------------------------------------
__global__ void k_softmax_gather(const float* __restrict__ t, const float* __restrict__ r,
                                 float* __restrict__ logd) {
    int b   = blockIdx.x;
    int tid = threadIdx.x;
    __shared__ float l[SS];
    __shared__ float lse;
    __shared__ int   am;
    if (tid < SS) l[tid] = logd[b * SS + tid];
    __syncthreads();
    if (tid == 0) {
        float m = l[0]; int a = 0;
        for (int s = 1; s < SS; s++) if (l[s] > m) { m = l[s]; a = s; }
        float sum = 0.f;
        for (int s = 0; s < SS; s++) sum += expf(l[s] - m);
        lse = m + logf(sum);
        am  = a;
        g_idx[b] = a;
    }
    __syncthreads();
    if (tid < SS) logd[b * SS + tid] = l[tid] - lse;
    int a = am;
    // gather 256 floats from each tensor as float4 (64 f4 each)
    if (tid < 64) {
        ((float4*)g_desc[0][b])[tid] =
            ((const float4*)(t + ((size_t)b * SS + a) * DD))[tid];
    } else if (tid < 128) {
        int i = tid - 64;
        ((float4*)g_desc[1][b])[i] =
            ((const float4*)(r + ((size_t)b * SS + a) * DD))[i];
    }
}

// ---------------------------------------------------------------------------
// K3: expert hidden layer, grouped by scene.
// grid = (4 ch-tiles, 64 scenes, 2 heads), 256 threads (1 channel/thread).
// Each block scans g_idx to build its scene's sample list, then processes
// samples in register-blocked chunks of NCH with the g-chunk staged in smem.
// ---------------------------------------------------------------------------
__global__ void __launch_bounds__(256) k_hidden(
        const float* __restrict__ Wth, const float* __restrict__ bth,
        const float* __restrict__ Wrh, const float* __restrict__ brh) {
    int tile  = blockIdx.x;     // 0..3
    int scene = blockIdx.y;     // 0..63
    int head  = blockIdx.z;     // 0..1
    const float* W    = head ? Wrh : Wth;
    const float* bias = head ? brh : bth;
    int tid = threadIdx.x;
    int ch  = tile * 256 + tid;

    __shared__ __align__(16) float gs[NCH][DD];
    __shared__ int   list[BB];
    __shared__ int   cnt_s;

    if (tid == 0) cnt_s = 0;
    __syncthreads();
    for (int b = tid; b < BB; b += 256)
        if (g_idx[b] == scene) { int p = atomicAdd(&cnt_s, 1); list[p] = b; }
    __syncthreads();
    int cnt = cnt_s;
    if (cnt == 0) return;

    float bv = bias[scene * CHN + ch];
    const float* Ws = W + (size_t)scene * DD * CHN;

    for (int c0 = 0; c0 < cnt; c0 += NCH) {
        int nc = min(NCH, cnt - c0);
        __syncthreads();   // previous chunk's gs reads done
        for (int i = tid; i < NCH * DD; i += 256) {
            int n = i >> 8, d = i & 255;
            gs[n][d] = (n < nc) ? g_desc[head][list[c0 + n]][d] : 0.f;
        }
        __syncthreads();

        float acc[NCH];
#pragma unroll
        for (int n = 0; n < NCH; n++) acc[n] = 0.f;

#pragma unroll 4
        for (int d4 = 0; d4 < DD / 4; d4++) {
            int d = d4 * 4;
            float w0 = Ws[(size_t)(d + 0) * CHN + ch];
            float w1 = Ws[(size_t)(d + 1) * CHN + ch];
            float w2 = Ws[(size_t)(d + 2) * CHN + ch];
            float w3 = Ws[(size_t)(d + 3) * CHN + ch];
#pragma unroll
            for (int n = 0; n < NCH; n++) {
                float4 g4 = *(const float4*)&gs[n][d];
                acc[n] = fmaf(g4.x, w0, acc[n]);
                acc[n] = fmaf(g4.y, w1, acc[n]);
                acc[n] = fmaf(g4.z, w2, acc[n]);
                acc[n] = fmaf(g4.w, w3, acc[n]);
            }
        }

        for (int n = 0; n < nc; n++) {
            float x = acc[n] + bv;
            float h = 0.5f * x * (1.0f + erff(x * 0.70710678118654752f));
            g_h[head][list[c0 + n]][ch] = h;
        }
    }
}

// ---------------------------------------------------------------------------
// K4: output projection h[1024] -> 3 (t) or 4 (rot) per sample, + bias.
// grid = (B, 2 heads), 128 threads, block reduction.
// pose layout: [B,7] = (x_t[3] | x_rot[4])
// ---------------------------------------------------------------------------
__global__ void k_proj(const float* __restrict__ Wto, const float* __restrict__ bto,
                       const float* __restrict__ Wro, const float* __restrict__ bro,
                       float* __restrict__ pose) {
    int b    = blockIdx.x;
    int head = blockIdx.y;
    int tid  = threadIdx.x;
    int scene = g_idx[b];
    int NO = head ? 4 : 3;
    const float* Wo = head ? (Wro + (size_t)scene * CHN * 4)
                           : (Wto + (size_t)scene * CHN * 3);
    const float* bo = head ? (bro + scene * 4) : (bto + scene * 3);
    const float* h  = g_h[head][b];

    float acc[4] = {0.f, 0.f, 0.f, 0.f};
    for (int c = tid; c < CHN; c += 128) {
        float hv = h[c];
        for (int o = 0; o < NO; o++) acc[o] = fmaf(hv, Wo[c * NO + o], acc[o]);
    }
    __shared__ float red[128][4];
#pragma unroll
    for (int o = 0; o < 4; o++) red[tid][o] = acc[o];
    __syncthreads();
    for (int s = 64; s; s >>= 1) {
        if (tid < s)
#pragma unroll
            for (int o = 0; o < 4; o++) red[tid][o] += red[tid + s][o];
        __syncthreads();
    }
    if (tid < NO) pose[b * 7 + (head ? 3 : 0) + tid] = red[0][tid] + bo[tid];
}

// ---------------------------------------------------------------------------
extern "C" void kernel_launch(void* const* d_in, const int* in_sizes, int n_in,
                              void* d_out, int out_size) {
    const float* t   = (const float*)d_in[0];
    const float* r   = (const float*)d_in[1];
    const float* Wsc = (const float*)d_in[2];
    const float* bsc = (const float*)d_in[3];
    const float* Wth = (const float*)d_in[4];
    const float* bth = (const float*)d_in[5];
    const float* Wto = (const float*)d_in[6];
    const float* bto = (const float*)d_in[7];
    const float* Wrh = (const float*)d_in[8];
    const float* brh = (const float*)d_in[9];
    const float* Wro = (const float*)d_in[10];
    const float* bro = (const float*)d_in[11];

    float* out  = (float*)d_out;
    float* pose = out;             // [B,7]
    float* logd = out + BB * 7;    // [B,S]

    k_logits<<<BB * SS / 8, 256>>>(t, r, Wsc, bsc, logd);
    k_softmax_gather<<<BB, 256>>>(t, r, logd);
    dim3 gh(4, 64, 2);
    k_hidden<<<gh, 256>>>(Wth, bth, Wrh, brh);
    dim3 gp(BB, 2);
    k_proj<<<gp, 128>>>(Wto, bto, Wro, bro, pose);
}

// round 4
// speedup vs baseline: 1.3186x; 1.3186x over previous
#include <cuda_runtime.h>
#include <math.h>

#define BB 1024
#define SS 64
#define DD 256
#define CHN 1024
#define NCH 16   // samples per chunk

typedef unsigned long long u64;

// scratch (device globals; no allocation allowed)
__device__ int   g_idx[BB];
__device__ int   g_cnt[SS];               // per-scene sample counts
__device__ int   g_list[SS][BB];          // per-scene sample lists (shared ordering!)
__device__ __align__(16) float g_desc[2][BB][DD];   // gathered descriptors (t, rot)

// ---- packed f32x2 helpers (Blackwell) --------------------------------------
__device__ __forceinline__ u64 dup2(float w) {
    unsigned u = __float_as_uint(w);
    u64 r; asm("mov.b64 %0, {%1, %2};" : "=l"(r) : "r"(u), "r"(u)); return r;
}
__device__ __forceinline__ float2 unpk2(u64 v) {
    unsigned lo, hi; asm("mov.b64 {%0, %1}, %2;" : "=r"(lo), "=r"(hi) : "l"(v));
    return make_float2(__uint_as_float(lo), __uint_as_float(hi));
}
__device__ __forceinline__ u64 ffma2(u64 a, u64 b, u64 c) {
    u64 d; asm("fma.rn.f32x2 %0, %1, %2, %3;" : "=l"(d) : "l"(a), "l"(b), "l"(c));
    return d;
}

// ---------------------------------------------------------------------------
// K1: logits[b,s] = dot(cat(t[b,s], rot[b,s]), W_scene) + b_scene
// one warp per (b,s); 512-length dot via float4.  Block 0 also zeroes g_cnt.
// ---------------------------------------------------------------------------
__global__ void k_logits(const float* __restrict__ t, const float* __restrict__ r,
                         const float* __restrict__ Wsc, const float* __restrict__ bsc,
                         float* __restrict__ logits) {
    if (blockIdx.x == 0 && threadIdx.x < SS) g_cnt[threadIdx.x] = 0;
    int w    = blockIdx.x * 8 + (threadIdx.x >> 5);
    int lane = threadIdx.x & 31;
    if (w >= BB * SS) return;
    const float4* t4 = (const float4*)(t + (size_t)w * DD);
    const float4* r4 = (const float4*)(r + (size_t)w * DD);
    const float4* W4 = (const float4*)Wsc;
    float acc = 0.f;
#pragma unroll
    for (int j = 0; j < 2; j++) {
        int k = j * 32 + lane;
        float4 a  = t4[k];
        float4 wa = W4[k];
        acc = fmaf(a.x, wa.x, acc); acc = fmaf(a.y, wa.y, acc);
        acc = fmaf(a.z, wa.z, acc); acc = fmaf(a.w, wa.w, acc);
        float4 b  = r4[k];
        float4 wb = W4[64 + k];
        acc = fmaf(b.x, wb.x, acc); acc = fmaf(b.y, wb.y, acc);
        acc = fmaf(b.z, wb.z, acc); acc = fmaf(b.w, wb.w, acc);
    }
#pragma unroll
    for (int o = 16; o; o >>= 1) acc += __shfl_down_sync(0xFFFFFFFFu, acc, o);
    if (lane == 0) logits[w] = acc + bsc[0];
}

// ---------------------------------------------------------------------------
// K2: log_softmax + argmax + global scene-list append + gather + pose bias
// ---------------------------------------------------------------------------
__global__ void k_softmax_gather(const float* __restrict__ t, const float* __restrict__ r,
                                 const float* __restrict__ bto, const float* __restrict__ bro,
                                 float* __restrict__ logd, float* __restrict__ pose) {
    int b   = blockIdx.x;
    int tid = threadIdx.x;
    __shared__ float l[SS];
    __shared__ float lse;
    __shared__ int   am;
    if (tid < SS) l[tid] = logd[b * SS + tid];
    __syncthreads();
    if (tid == 0) {
        float m = l[0]; int a = 0;
        for (int s = 1; s < SS; s++) if (l[s] > m) { m = l[s]; a = s; }
        float sum = 0.f;
        for (int s = 0; s < SS; s++) sum += expf(l[s] - m);
        lse = m + logf(sum);
        am  = a;
        g_idx[b] = a;
        int p = atomicAdd(&g_cnt[a], 1);   // single global ordering, seen by ALL blocks
        g_list[a][p] = b;
    }
    __syncthreads();
    if (tid < SS) logd[b * SS + tid] = l[tid] - lse;
    int a = am;
    if (tid >= 224) {                       // pose bias init (accumulated by k_hidden)
        int o = tid - 224;
        if (o < 3)      pose[b * 7 + o] = bto[a * 3 + o];
        else if (o < 7) pose[b * 7 + o] = bro[a * 4 + (o - 3)];
    }
    if (tid < 64) {
        ((float4*)g_desc[0][b])[tid] =
            ((const float4*)(t + ((size_t)b * SS + a) * DD))[tid];
    } else if (tid < 128) {
        int i = tid - 64;
        ((float4*)g_desc[1][b])[i] =
            ((const float4*)(r + ((size_t)b * SS + a) * DD))[i];
    }
}

// ---------------------------------------------------------------------------
// K3: fused expert hidden layer + gelu + output projection.
// grid = (2 ch-tiles, 64 scenes, 2 heads * 4 chunk-slots), 256 threads.
// Thread handles 2 channels (ch0, ch0+256) x 16 samples; accumulators are
// packed f32x2 sample-pairs via fma.rn.f32x2. All blocks read the SAME
// g_list ordering, so splitting positions across jc blocks is consistent.
// ---------------------------------------------------------------------------
__global__ void __launch_bounds__(256) k_hidden(
        const float* __restrict__ Wth, const float* __restrict__ bth,
        const float* __restrict__ Wto,
        const float* __restrict__ Wrh, const float* __restrict__ brh,
        const float* __restrict__ Wro,
        float* __restrict__ pose) {
    int tile  = blockIdx.x;            // 0..1 (512 channels each)
    int scene = blockIdx.y;            // 0..63
    int head  = blockIdx.z & 1;
    int jc    = blockIdx.z >> 1;       // chunk slot 0..3
    int tid   = threadIdx.x;
    int lane  = tid & 31;

    int cnt = g_cnt[scene];
    if (jc * NCH >= cnt) return;
    const int* list = g_list[scene];

    const float* W    = head ? Wrh : Wth;
    const float* bias = head ? brh : bth;
    const float* Wo   = head ? Wro : Wto;
    const int    NO   = head ? 4 : 3;
    const int    ooff = head ? 3 : 0;

    __shared__ __align__(16) float gs[DD][NCH + 2];   // transposed, padded
    __shared__ float part[NCH][4];

    int ch0 = tile * 512 + tid;        // channels ch0 and ch0+256
    int ch1 = ch0 + 256;
    const float* Ws = W + (size_t)scene * DD * CHN;
    float bv0 = bias[scene * CHN + ch0];
    float bv1 = bias[scene * CHN + ch1];
    float woA[4], woB[4];
#pragma unroll
    for (int o = 0; o < 4; o++) {
        woA[o] = (o < NO) ? Wo[((size_t)scene * CHN + ch0) * NO + o] : 0.f;
        woB[o] = (o < NO) ? Wo[((size_t)scene * CHN + ch1) * NO + o] : 0.f;
    }

    for (int c0 = jc * NCH; c0 < cnt; c0 += 4 * NCH) {
        int nc = min(NCH, cnt - c0);
        __syncthreads();    // protect gs/part reuse across chunks
        {
            const float* gd = &g_desc[head][0][0];
#pragma unroll 4
            for (int n = 0; n < NCH; n++) {
                float v = (n < nc) ? gd[(size_t)list[c0 + n] * DD + tid] : 0.f;
                gs[tid][n] = v;
            }
        }
        if (tid < NCH * 4) part[tid >> 2][tid & 3] = 0.f;
        __syncthreads();

        u64 accA[8], accB[8];
#pragma unroll
        for (int j = 0; j < 8; j++) { accA[j] = 0ull; accB[j] = 0ull; }

#pragma unroll 4
        for (int d = 0; d < DD; d++) {
            float w0 = Ws[(size_t)d * CHN + ch0];
            float w1 = Ws[(size_t)d * CHN + ch1];
            u64 w0d = dup2(w0);
            u64 w1d = dup2(w1);
            const u64* grow = (const u64*)&gs[d][0];
#pragma unroll
            for (int j = 0; j < 8; j++) {
                u64 g = grow[j];
                accA[j] = ffma2(g, w0d, accA[j]);
                accB[j] = ffma2(g, w1d, accB[j]);
            }
        }

        // epilogue: gelu + projection partials + warp reduce + smem accumulate
#pragma unroll
        for (int j = 0; j < 8; j++) {
            float2 ga = unpk2(accA[j]);
            float2 gb = unpk2(accB[j]);
            float x0s[2] = {ga.x, ga.y};
            float x1s[2] = {gb.x, gb.y};
#pragma unroll
            for (int q = 0; q < 2; q++) {
                int n = 2 * j + q;
                if (n < nc) {                       // warp-uniform
                    float x0 = x0s[q] + bv0;
                    float x1 = x1s[q] + bv1;
                    float h0 = 0.5f * x0 * (1.0f + erff(x0 * 0.70710678118654752f));
                    float h1 = 0.5f * x1 * (1.0f + erff(x1 * 0.70710678118654752f));
                    float p0 = h0 * woA[0] + h1 * woB[0];
                    float p1 = h0 * woA[1] + h1 * woB[1];
                    float p2 = h0 * woA[2] + h1 * woB[2];
                    float p3 = h0 * woA[3] + h1 * woB[3];
#pragma unroll
                    for (int off = 16; off; off >>= 1) {
                        p0 += __shfl_down_sync(0xFFFFFFFFu, p0, off);
                        p1 += __shfl_down_sync(0xFFFFFFFFu, p1, off);
                        p2 += __shfl_down_sync(0xFFFFFFFFu, p2, off);
                        p3 += __shfl_down_sync(0xFFFFFFFFu, p3, off);
                    }
                    if (lane == 0) {
                        atomicAdd(&part[n][0], p0);
                        atomicAdd(&part[n][1], p1);
                        atomicAdd(&part[n][2], p2);
                        atomicAdd(&part[n][3], p3);
                    }
                }
            }
        }
        __syncthreads();
        if (tid < NCH * 4) {
            int n = tid >> 2, o = tid & 3;
            if (n < nc && o < NO)
                atomicAdd(&pose[(size_t)list[c0 + n] * 7 + ooff + o], part[n][o]);
        }
    }
}

// ---------------------------------------------------------------------------
extern "C" void kernel_launch(void* const* d_in, const int* in_sizes, int n_in,
                              void* d_out, int out_size) {
    const float* t   = (const float*)d_in[0];
    const float* r   = (const float*)d_in[1];
    const float* Wsc = (const float*)d_in[2];
    const float* bsc = (const float*)d_in[3];
    const float* Wth = (const float*)d_in[4];
    const float* bth = (const float*)d_in[5];
    const float* Wto = (const float*)d_in[6];
    const float* bto = (const float*)d_in[7];
    const float* Wrh = (const float*)d_in[8];
    const float* brh = (const float*)d_in[9];
    const float* Wro = (const float*)d_in[10];
    const float* bro = (const float*)d_in[11];

    float* out  = (float*)d_out;
    float* pose = out;             // [B,7]
    float* logd = out + BB * 7;    // [B,S]

    k_logits<<<BB * SS / 8, 256>>>(t, r, Wsc, bsc, logd);
    k_softmax_gather<<<BB, 256>>>(t, r, bto, bro, logd, pose);
    dim3 gh(2, 64, 8);
    k_hidden<<<gh, 256>>>(Wth, bth, Wto, Wrh, brh, Wro, pose);
}

// round 6
// speedup vs baseline: 1.7540x; 1.3302x over previous
#include <cuda_runtime.h>
#include <math.h>

#define BB 1024
#define SS 64
#define DD 256
#define CHN 1024
#define NCH 8    // samples per chunk (k_hidden)

typedef unsigned long long u64;

// scratch (device globals; no allocation allowed)
__device__ int   g_idx[BB];
__device__ int   g_cnt[SS];               // per-scene sample counts
__device__ int   g_list[SS][BB];          // per-scene sample lists (global ordering)
__device__ __align__(16) float g_desc[2][BB][DD];   // gathered descriptors (t, rot)

// ---- packed f32x2 helpers (Blackwell) --------------------------------------
__device__ __forceinline__ u64 dup2(float w) {
    unsigned u = __float_as_uint(w);
    u64 r; asm("mov.b64 %0, {%1, %2};" : "=l"(r) : "r"(u), "r"(u)); return r;
}
__device__ __forceinline__ float2 unpk2(u64 v) {
    unsigned lo, hi; asm("mov.b64 {%0, %1}, %2;" : "=r"(lo), "=r"(hi) : "l"(v));
    return make_float2(__uint_as_float(lo), __uint_as_float(hi));
}
__device__ __forceinline__ u64 ffma2(u64 a, u64 b, u64 c) {
    u64 d; asm("fma.rn.f32x2 %0, %1, %2, %3;" : "=l"(d) : "l"(a), "l"(b), "l"(c));
    return d;
}

// ---------------------------------------------------------------------------
// K1: logits for 2 rows per warp (8 LDG.128 in flight, W regs shared).
// Block 0 also zeroes g_cnt (safe: consumers are in later kernels).
// ---------------------------------------------------------------------------
__global__ void __launch_bounds__(256) k_logits(
        const float* __restrict__ t, const float* __restrict__ r,
        const float* __restrict__ Wsc, const float* __restrict__ bsc,
        float* __restrict__ logits) {
    if (blockIdx.x == 0 && threadIdx.x < SS) g_cnt[threadIdx.x] = 0;
    int g    = blockIdx.x * 8 + (threadIdx.x >> 5);   // warp id
    int lane = threadIdx.x & 31;
    int w0   = g * 2;
    if (w0 >= BB * SS) return;
    const float4* t40 = (const float4*)(t + (size_t)w0 * DD);
    const float4* r40 = (const float4*)(r + (size_t)w0 * DD);
    const float4* t41 = t40 + DD / 4;
    const float4* r41 = r40 + DD / 4;
    const float4* W4  = (const float4*)Wsc;
    float acc0 = 0.f, acc1 = 0.f;
#pragma unroll
    for (int j = 0; j < 2; j++) {
        int k = j * 32 + lane;
        float4 wa = W4[k];
        float4 wb = W4[64 + k];
        float4 a0 = t40[k], b0 = r40[k];
        float4 a1 = t41[k], b1 = r41[k];
        acc0 = fmaf(a0.x, wa.x, acc0); acc0 = fmaf(a0.y, wa.y, acc0);
        acc0 = fmaf(a0.z, wa.z, acc0); acc0 = fmaf(a0.w, wa.w, acc0);
        acc0 = fmaf(b0.x, wb.x, acc0); acc0 = fmaf(b0.y, wb.y, acc0);
        acc0 = fmaf(b0.z, wb.z, acc0); acc0 = fmaf(b0.w, wb.w, acc0);
        acc1 = fmaf(a1.x, wa.x, acc1); acc1 = fmaf(a1.y, wa.y, acc1);
        acc1 = fmaf(a1.z, wa.z, acc1); acc1 = fmaf(a1.w, wa.w, acc1);
        acc1 = fmaf(b1.x, wb.x, acc1); acc1 = fmaf(b1.y, wb.y, acc1);
        acc1 = fmaf(b1.z, wb.z, acc1); acc1 = fmaf(b1.w, wb.w, acc1);
    }
#pragma unroll
    for (int o = 16; o; o >>= 1) {
        acc0 += __shfl_xor_sync(0xFFFFFFFFu, acc0, o);
        acc1 += __shfl_xor_sync(0xFFFFFFFFu, acc1, o);
    }
    if (lane == 0) {
        float bb = bsc[0];
        logits[w0]     = acc0 + bb;
        logits[w0 + 1] = acc1 + bb;
    }
}

// ---------------------------------------------------------------------------
// K2: log_softmax + argmax (warp-parallel) + scene-list append + gather + bias
// ---------------------------------------------------------------------------
__global__ void k_softmax_gather(const float* __restrict__ t, const float* __restrict__ r,
                                 const float* __restrict__ bto, const float* __restrict__ bro,
                                 float* __restrict__ logd, float* __restrict__ pose) {
    int b    = blockIdx.x;
    int tid  = threadIdx.x;
    int wid  = tid >> 5;
    int lane = tid & 31;
    __shared__ float l[SS];
    __shared__ float lse;
    __shared__ int   am;
    if (tid < SS) l[tid] = logd[b * SS + tid];
    __syncthreads();
    if (wid == 0) {
        float v0 = l[lane], v1 = l[lane + 32];
        float m; int a;
        if (v1 > v0) { m = v1; a = lane + 32; } else { m = v0; a = lane; }
#pragma unroll
        for (int o = 16; o; o >>= 1) {
            float mo = __shfl_down_sync(0xFFFFFFFFu, m, o);
            int   ao = __shfl_down_sync(0xFFFFFFFFu, a, o);
            if (mo > m || (mo == m && ao < a)) { m = mo; a = ao; }
        }
        m = __shfl_sync(0xFFFFFFFFu, m, 0);
        a = __shfl_sync(0xFFFFFFFFu, a, 0);
        float s = expf(v0 - m) + expf(v1 - m);
#pragma unroll
        for (int o = 16; o; o >>= 1) s += __shfl_xor_sync(0xFFFFFFFFu, s, o);
        if (lane == 0) {
            lse = m + logf(s);
            am  = a;
            g_idx[b] = a;
            int p = atomicAdd(&g_cnt[a], 1);   // single global ordering
            g_list[a][p] = b;
        }
    }
    __syncthreads();
    if (tid < SS) logd[b * SS + tid] = l[tid] - lse;
    int a = am;
    if (tid >= 224) {                          // pose bias init
        int o = tid - 224;
        if (o < 3)      pose[b * 7 + o] = bto[a * 3 + o];
        else if (o < 7) pose[b * 7 + o] = bro[a * 4 + (o - 3)];
    }
    if (tid < 64) {
        ((float4*)g_desc[0][b])[tid] =
            ((const float4*)(t + ((size_t)b * SS + a) * DD))[tid];
    } else if (tid < 128) {
        int i = tid - 64;
        ((float4*)g_desc[1][b])[i] =
            ((const float4*)(r + ((size_t)b * SS + a) * DD))[i];
    }
}

// ---------------------------------------------------------------------------
// K3: fused expert hidden layer + gelu + output projection.
// grid = (64 scenes, 2 heads, 4 jc chunk-slots), 256 threads.
// Thread owns 4 CONSECUTIVE channels (float4 weight LDG.128) x 8 samples
// (4 f32x2 pairs per channel) -> 16 u64 accumulators.
// ---------------------------------------------------------------------------
__global__ void __launch_bounds__(256, 3) k_hidden(
        const float* __restrict__ Wth, const float* __restrict__ bth,
        const float* __restrict__ Wto,
        const float* __restrict__ Wrh, const float* __restrict__ brh,
        const float* __restrict__ Wro,
        float* __restrict__ pose) {
    int scene = blockIdx.x;            // 0..63
    int head  = blockIdx.y;            // 0..1
    int jc    = blockIdx.z;            // chunk slot 0..3
    int tid   = threadIdx.x;
    int lane  = tid & 31;

    int cnt = g_cnt[scene];
    if (jc * NCH >= cnt) return;
    const int* list = g_list[scene];

    const float* W    = head ? Wrh : Wth;
    const float* bias = head ? brh : bth;
    const float* Wo   = head ? Wro : Wto;
    const int    NO   = head ? 4 : 3;
    const int    ooff = head ? 3 : 0;

    __shared__ __align__(16) float gs[DD][NCH + 2];   // transposed, padded
    __shared__ float part[NCH][4];

    int ch = tid * 4;                                  // 4 consecutive channels
    const float* Ws = W + (size_t)scene * DD * CHN;

    for (int c0 = jc * NCH; c0 < cnt; c0 += 4 * NCH) {
        int nc = min(NCH, cnt - c0);
        __syncthreads();    // protect gs/part reuse across chunks
        {
            const float* gd = &g_desc[head][0][0];
#pragma unroll
            for (int n = 0; n < NCH; n++) {
                float v = (n < nc) ? gd[(size_t)list[c0 + n] * DD + tid] : 0.f;
                gs[tid][n] = v;
            }
        }
        if (tid < NCH * 4) part[tid >> 2][tid & 3] = 0.f;
        __syncthreads();

        u64 acc[4][4];      // [channel][sample-pair]
#pragma unroll
        for (int c = 0; c < 4; c++)
#pragma unroll
            for (int p = 0; p < 4; p++) acc[c][p] = 0ull;

#pragma unroll 4
        for (int d = 0; d < DD; d++) {
            float4 wv = *(const float4*)&Ws[(size_t)d * CHN + ch];
            u64 wd[4] = {dup2(wv.x), dup2(wv.y), dup2(wv.z), dup2(wv.w)};
            const u64* grow = (const u64*)&gs[d][0];
#pragma unroll
            for (int p = 0; p < 4; p++) {
                u64 gp = grow[p];
#pragma unroll
                for (int c = 0; c < 4; c++)
                    acc[c][p] = ffma2(gp, wd[c], acc[c][p]);
            }
        }

        // epilogue (loads here to keep main-loop register pressure low)
        float4 bv = *(const float4*)&bias[(size_t)scene * CHN + ch];
        float bvs[4] = {bv.x, bv.y, bv.z, bv.w};
        float wo[4][4];
#pragma unroll
        for (int c = 0; c < 4; c++)
#pragma unroll
            for (int o = 0; o < 4; o++)
                wo[c][o] = (o < NO) ? Wo[((size_t)scene * CHN + ch + c) * NO + o] : 0.f;

#pragma unroll
        for (int p = 0; p < 4; p++) {
            float2 xs[4];
#pragma unroll
            for (int c = 0; c < 4; c++) xs[c] = unpk2(acc[c][p]);
#pragma unroll
            for (int q = 0; q < 2; q++) {
                int n = 2 * p + q;
                if (n < nc) {                       // warp-uniform
                    float pv[4] = {0.f, 0.f, 0.f, 0.f};
#pragma unroll
                    for (int c = 0; c < 4; c++) {
                        float x = (q ? xs[c].y : xs[c].x) + bvs[c];
                        float h = 0.5f * x * (1.0f + erff(x * 0.70710678118654752f));
#pragma unroll
                        for (int o = 0; o < 4; o++) pv[o] = fmaf(h, wo[c][o], pv[o]);
                    }
#pragma unroll
                    for (int off = 16; off; off >>= 1) {
                        pv[0] += __shfl_down_sync(0xFFFFFFFFu, pv[0], off);
                        pv[1] += __shfl_down_sync(0xFFFFFFFFu, pv[1], off);
                        pv[2] += __shfl_down_sync(0xFFFFFFFFu, pv[2], off);
                        pv[3] += __shfl_down_sync(0xFFFFFFFFu, pv[3], off);
                    }
                    if (lane == 0) {
                        atomicAdd(&part[n][0], pv[0]);
                        atomicAdd(&part[n][1], pv[1]);
                        atomicAdd(&part[n][2], pv[2]);
                        atomicAdd(&part[n][3], pv[3]);
                    }
                }
            }
        }
        __syncthreads();
        if (tid < NCH * 4) {
            int n = tid >> 2, o = tid & 3;
            if (n < nc && o < NO)
                atomicAdd(&pose[(size_t)list[c0 + n] * 7 + ooff + o], part[n][o]);
        }
    }
}

// ---------------------------------------------------------------------------
extern "C" void kernel_launch(void* const* d_in, const int* in_sizes, int n_in,
                              void* d_out, int out_size) {
    const float* t   = (const float*)d_in[0];
    const float* r   = (const float*)d_in[1];
    const float* Wsc = (const float*)d_in[2];
    const float* bsc = (const float*)d_in[3];
    const float* Wth = (const float*)d_in[4];
    const float* bth = (const float*)d_in[5];
    const float* Wto = (const float*)d_in[6];
    const float* bto = (const float*)d_in[7];
    const float* Wrh = (const float*)d_in[8];
    const float* brh = (const float*)d_in[9];
    const float* Wro = (const float*)d_in[10];
    const float* bro = (const float*)d_in[11];

    float* out  = (float*)d_out;
    float* pose = out;             // [B,7]
    float* logd = out + BB * 7;    // [B,S]

    k_logits<<<BB * SS / 16, 256>>>(t, r, Wsc, bsc, logd);
    k_softmax_gather<<<BB, 256>>>(t, r, bto, bro, logd, pose);
    dim3 gh(64, 2, 4);
    k_hidden<<<gh, 256>>>(Wth, bth, Wto, Wrh, brh, Wro, pose);
}